// round 16
// baseline (speedup 1.0000x reference)
#include <cuda_runtime.h>
#include <cuda_fp16.h>
#include <cuda_bf16.h>
#include <math.h>
#include <stdint.h>

#define N_NODES  524288
#define N_EDGES  2097152
#define N_GRAPHS 16384
#define COMP_DIM 3539
#define PROT_DIM 384
#define GNN_HID  64
#define G_EMB    128
#define HID      256
#define K_TOT    (G_EMB + COMP_DIM + PROT_DIM)   /* 4051 */
#define KP2      4096

#define SCAN_BLK   1024
#define NSCAN_BLKS (N_NODES / SCAN_BLK)   /* 512 */

// -------------------- scratch (static device memory; no allocs) --------------------
__device__ float g_dinv[N_NODES];
__device__ float g_s[N_NODES];
__device__ float g_acc1[N_NODES];
__device__ __half g_h2s[N_NODES * GNN_HID];
__device__ __half g_x2[N_NODES * GNN_HID];
__device__ int g_gstart[N_GRAPHS + 1];
__device__ int g_ecnt[N_NODES];          // zero at entry: static init on call 1, k_gather zeroes on replays
__device__ int g_eoff[N_NODES];
__device__ int g_cur[N_NODES];
__device__ int g_bsum[NSCAN_BLKS];
__device__ int g_erow[N_EDGES];
__device__ __half g_a16[(size_t)N_GRAPHS * KP2];
__device__ __half g_w16[(size_t)HID * KP2];

// -------------------- helpers --------------------
__device__ __forceinline__ void split2b(float v, __nv_bfloat16& h, __nv_bfloat16& l) {
    h = __float2bfloat16(v);
    l = __float2bfloat16(v - __bfloat162float(h));
}

__device__ __forceinline__ uint32_t packh2(__half a, __half b) {
    return ((uint32_t)__half_as_ushort(b) << 16) | (uint32_t)__half_as_ushort(a);
}

__device__ __forceinline__ uint32_t s2u(const void* p) {
    uint32_t a;
    asm("{ .reg .u64 t; cvta.to.shared.u64 t, %1; cvt.u32.u64 %0, t; }" : "=r"(a) : "l"(p));
    return a;
}

#define CP16(dst, src) \
    asm volatile("cp.async.cg.shared.global [%0], [%1], 16;" :: "r"(dst), "l"(src) : "memory")

__device__ __forceinline__ void ldsm4(uint32_t& r0, uint32_t& r1, uint32_t& r2, uint32_t& r3,
                                      uint32_t addr) {
    asm volatile("ldmatrix.sync.aligned.m8n8.x4.shared.b16 {%0,%1,%2,%3}, [%4];"
                 : "=r"(r0), "=r"(r1), "=r"(r2), "=r"(r3) : "r"(addr));
}

__device__ __forceinline__ void mma16816h(float* c, const uint32_t* a, const uint32_t* b) {
    asm volatile(
        "mma.sync.aligned.m16n8k16.row.col.f32.f16.f16.f32 "
        "{%0,%1,%2,%3}, {%4,%5,%6,%7}, {%8,%9}, {%0,%1,%2,%3};"
        : "+f"(c[0]), "+f"(c[1]), "+f"(c[2]), "+f"(c[3])
        : "r"(a[0]), "r"(a[1]), "r"(a[2]), "r"(a[3]), "r"(b[0]), "r"(b[1]));
}

__device__ __forceinline__ void mma16816b(float* c, const uint32_t* a, const uint32_t* b) {
    asm volatile(
        "mma.sync.aligned.m16n8k16.row.col.f32.bf16.bf16.f32 "
        "{%0,%1,%2,%3}, {%4,%5,%6,%7}, {%8,%9}, {%0,%1,%2,%3};"
        : "+f"(c[0]), "+f"(c[1]), "+f"(c[2]), "+f"(c[3])
        : "r"(a[0]), "r"(a[1]), "r"(a[2]), "r"(a[3]), "r"(b[0]), "r"(b[1]));
}

// -------------------- GEMM geometry --------------------
#define BM 128
#define BN 256
#define BK 32
#define NCHUNK (KP2 / BK)     /* 128 */
#define NSTAGE 3
#define SKA 40
#define THR 512

#define SZ_A   (128 * SKA * 2)
#define SZ_B   (256 * SKA * 2)
#define OFF_A  0
#define OFF_B  (SZ_A)
#define STAGE_SZ (SZ_A + SZ_B)
#define OFF_BF1 (NSTAGE * STAGE_SZ)
#define OFF_WF2 (OFF_BF1 + 1024)
#define OFF_RED (OFF_WF2 + 1024)
#define SMEM_BYTES (OFF_RED + 2048)

// layer2t smem layout
#define L2_SU   0
#define L2_SDV  512
#define L2_SW1  1024
#define L2_SB1  1280
#define L2_XH   1536
#define L2_XL   (L2_XH + 20480)
#define L2_WH   (L2_XL + 20480)
#define L2_WL   (L2_WH + 10240)
#define L2_SMEM (L2_WL + 10240)

// -------------------- setup / bucketing kernels --------------------

__global__ void k_hist(const int* __restrict__ ei) {
    int e = blockIdx.x * blockDim.x + threadIdx.x;
    if (e < N_EDGES) atomicAdd(&g_ecnt[ei[N_EDGES + e]], 1);
}

// block scan + fused dinv/s/acc1 + graph bounds (absorbed former k_init)
__global__ __launch_bounds__(SCAN_BLK) void k_scan1(const float* __restrict__ node_x,
                                                    const int* __restrict__ batch) {
    __shared__ int sh[SCAN_BLK];
    int t = threadIdx.x;
    int base = blockIdx.x * SCAN_BLK;
    int i = base + t;
    int v = g_ecnt[i];
    sh[t] = v;
    __syncthreads();
#pragma unroll
    for (int off = 1; off < SCAN_BLK; off <<= 1) {
        int x = (t >= off) ? sh[t - off] : 0;
        __syncthreads();
        sh[t] += x;
        __syncthreads();
    }
    g_eoff[i] = sh[t] - v;
    if (t == SCAN_BLK - 1) g_bsum[blockIdx.x] = sh[t];
    float d = rsqrtf(1.0f + (float)v);
    g_dinv[i] = d;
    float s = d * node_x[i];
    g_s[i] = s;
    g_acc1[i] = s;
    // graph bounds from sorted batch
    int b = batch[i];
    if (i == 0) {
        for (int g = 0; g <= b; g++) g_gstart[g] = 0;
    } else {
        int bp = batch[i - 1];
        for (int g = bp + 1; g <= b; g++) g_gstart[g] = i;
    }
    if (i == N_NODES - 1) {
        for (int g = b + 1; g <= N_GRAPHS; g++) g_gstart[g] = N_NODES;
    }
}

__global__ __launch_bounds__(NSCAN_BLKS) void k_scan2() {
    __shared__ int sh[NSCAN_BLKS];
    int t = threadIdx.x;
    int v = g_bsum[t];
    sh[t] = v;
    __syncthreads();
#pragma unroll
    for (int off = 1; off < NSCAN_BLKS; off <<= 1) {
        int x = (t >= off) ? sh[t - off] : 0;
        __syncthreads();
        sh[t] += x;
        __syncthreads();
    }
    g_bsum[t] = sh[t] - v;
}

__global__ __launch_bounds__(SCAN_BLK) void k_scan3() {
    int i = blockIdx.x * SCAN_BLK + threadIdx.x;
    int o = g_eoff[i] + g_bsum[blockIdx.x];
    g_eoff[i] = o;
    g_cur[i] = o;
}

// Fused: bucket fill + layer-1 scalar scatter (single pass over edges)
__global__ void k_bucket_scat(const int* __restrict__ ei) {
    int e = blockIdx.x * blockDim.x + threadIdx.x;
    if (e < N_EDGES) {
        int r = ei[e];
        int c = ei[N_EDGES + e];
        int pos = atomicAdd(&g_cur[c], 1);
        g_erow[pos] = r;
        atomicAdd(&g_acc1[c], g_s[r]);
    }
}

// Tensor-core layer2 (bf16 3-pass, proven): h2s = dinv*(x1@W2) -> fp16
__global__ void __launch_bounds__(256) k_layer2t(const float* __restrict__ W1,
                                                 const float* __restrict__ b1,
                                                 const float* __restrict__ W2) {
    extern __shared__ char sm[];
    float* su  = (float*)(sm + L2_SU);
    float* sdv = (float*)(sm + L2_SDV);
    float* sW1 = (float*)(sm + L2_SW1);
    float* sb1 = (float*)(sm + L2_SB1);
    __nv_bfloat16* sXh = (__nv_bfloat16*)(sm + L2_XH);
    __nv_bfloat16* sXl = (__nv_bfloat16*)(sm + L2_XL);
    __nv_bfloat16* sWh = (__nv_bfloat16*)(sm + L2_WH);
    __nv_bfloat16* sWl = (__nv_bfloat16*)(sm + L2_WL);

    int tid = threadIdx.x;
    int node0 = blockIdx.x * 128;

    if (tid < 64) { sW1[tid] = W1[tid]; sb1[tid] = b1[tid]; }
    if (tid < 128) {
        int n = node0 + tid;
        float dv = g_dinv[n];
        sdv[tid] = dv;
        su[tid] = dv * g_acc1[n];
    }
    for (int idx = tid; idx < 64 * 64; idx += 256) {
        int k = idx >> 6, n = idx & 63;
        __nv_bfloat16 h, l;
        split2b(W2[idx], h, l);
        int off = (k >> 5) * (64 * SKA) + n * SKA + (k & 31);
        sWh[off] = h; sWl[off] = l;
    }
    __syncthreads();

    for (int idx = tid; idx < 128 * 64; idx += 256) {
        int m = idx >> 6, k = idx & 63;
        float x = fmaxf(su[m] * sW1[k] + sb1[k], 0.0f);
        __nv_bfloat16 h, l;
        split2b(x, h, l);
        int off = (k >> 5) * (128 * SKA) + m * SKA + (k & 31);
        sXh[off] = h; sXl[off] = l;
    }
    __syncthreads();

    int wid = tid >> 5, lane = tid & 31;
    int mw = wid >> 1, nw = wid & 1;
    int g = lane >> 2, tig = lane & 3;

    float acc[2][4][4];
#pragma unroll
    for (int mt = 0; mt < 2; mt++)
#pragma unroll
        for (int nt = 0; nt < 4; nt++)
#pragma unroll
            for (int e = 0; e < 4; e++) acc[mt][nt][e] = 0.0f;

#pragma unroll
    for (int ks = 0; ks < 4; ks++) {
        int ch = ks >> 1, kc = (ks & 1) * 16;
        const __nv_bfloat16* Ah = sXh + ch * (128 * SKA);
        const __nv_bfloat16* Al = sXl + ch * (128 * SKA);
        const __nv_bfloat16* Bh = sWh + ch * (64 * SKA);
        const __nv_bfloat16* Bl = sWl + ch * (64 * SKA);
        uint32_t a[2][4], b[4][2];
#pragma unroll
        for (int mt = 0; mt < 2; mt++) {
            const __nv_bfloat16* p = Al + (mw * 32 + mt * 16 + g) * SKA + kc + tig * 2;
            a[mt][0] = *(const uint32_t*)p;
            a[mt][1] = *(const uint32_t*)(p + 8 * SKA);
            a[mt][2] = *(const uint32_t*)(p + 8);
            a[mt][3] = *(const uint32_t*)(p + 8 * SKA + 8);
        }
#pragma unroll
        for (int nt = 0; nt < 4; nt++) {
            const __nv_bfloat16* p = Bh + (nw * 32 + nt * 8 + g) * SKA + kc + tig * 2;
            b[nt][0] = *(const uint32_t*)p;
            b[nt][1] = *(const uint32_t*)(p + 8);
        }
#pragma unroll
        for (int mt = 0; mt < 2; mt++)
#pragma unroll
            for (int nt = 0; nt < 4; nt++) mma16816b(acc[mt][nt], a[mt], b[nt]);
#pragma unroll
        for (int mt = 0; mt < 2; mt++) {
            const __nv_bfloat16* p = Ah + (mw * 32 + mt * 16 + g) * SKA + kc + tig * 2;
            a[mt][0] = *(const uint32_t*)p;
            a[mt][1] = *(const uint32_t*)(p + 8 * SKA);
            a[mt][2] = *(const uint32_t*)(p + 8);
            a[mt][3] = *(const uint32_t*)(p + 8 * SKA + 8);
        }
#pragma unroll
        for (int mt = 0; mt < 2; mt++)
#pragma unroll
            for (int nt = 0; nt < 4; nt++) mma16816b(acc[mt][nt], a[mt], b[nt]);
#pragma unroll
        for (int nt = 0; nt < 4; nt++) {
            const __nv_bfloat16* p = Bl + (nw * 32 + nt * 8 + g) * SKA + kc + tig * 2;
            b[nt][0] = *(const uint32_t*)p;
            b[nt][1] = *(const uint32_t*)(p + 8);
        }
#pragma unroll
        for (int mt = 0; mt < 2; mt++)
#pragma unroll
            for (int nt = 0; nt < 4; nt++) mma16816b(acc[mt][nt], a[mt], b[nt]);
    }

#pragma unroll
    for (int mt = 0; mt < 2; mt++) {
        int r0 = mw * 32 + mt * 16 + g;
        float dv0 = sdv[r0], dv1 = sdv[r0 + 8];
#pragma unroll
        for (int nt = 0; nt < 4; nt++) {
            int col = nw * 32 + nt * 8 + tig * 2;
            size_t o0 = (size_t)(node0 + r0) * GNN_HID + col;
            size_t o1 = (size_t)(node0 + r0 + 8) * GNN_HID + col;
            *(__half2*)&g_h2s[o0] =
                __floats2half2_rn(dv0 * acc[mt][nt][0], dv0 * acc[mt][nt][1]);
            *(__half2*)&g_h2s[o1] =
                __floats2half2_rn(dv1 * acc[mt][nt][2], dv1 * acc[mt][nt][3]);
        }
    }
}

// Gather + relu -> x2 (fp16). One warp per node; lane owns channels (2l, 2l+1).
// Lane 0 zeroes g_ecnt[node] after last use (readies replay for k_hist).
__global__ void k_gather(const float* __restrict__ b2) {
    int gt = blockIdx.x * blockDim.x + threadIdx.x;
    int node = gt >> 5;
    int lane = gt & 31;
    if (node >= N_NODES) return;

    int start = g_eoff[node];
    int cnt = g_ecnt[node];
    if (lane == 0) g_ecnt[node] = 0;     // last reader; reset for next replay
    const __half2* selfp = (const __half2*)&g_h2s[(size_t)node * GNN_HID];
    float2 sv = __half22float2(selfp[lane]);
    float a0 = sv.x, a1 = sv.y;
    float b0 = 0.f, b1 = 0.f, c0 = 0.f, c1 = 0.f, d0 = 0.f, d1 = 0.f;

    int base = 0;
    for (; base + 4 <= cnt; base += 4) {
        int r0 = __ldg(&g_erow[start + base + 0]);
        int r1 = __ldg(&g_erow[start + base + 1]);
        int r2 = __ldg(&g_erow[start + base + 2]);
        int r3 = __ldg(&g_erow[start + base + 3]);
        float2 v0 = __half22float2(((const __half2*)&g_h2s[(size_t)r0 * GNN_HID])[lane]);
        float2 v1 = __half22float2(((const __half2*)&g_h2s[(size_t)r1 * GNN_HID])[lane]);
        float2 v2 = __half22float2(((const __half2*)&g_h2s[(size_t)r2 * GNN_HID])[lane]);
        float2 v3 = __half22float2(((const __half2*)&g_h2s[(size_t)r3 * GNN_HID])[lane]);
        a0 += v0.x; a1 += v0.y;
        b0 += v1.x; b1 += v1.y;
        c0 += v2.x; c1 += v2.y;
        d0 += v3.x; d1 += v3.y;
    }
    if (base + 2 <= cnt) {
        int r0 = __ldg(&g_erow[start + base + 0]);
        int r1 = __ldg(&g_erow[start + base + 1]);
        float2 v0 = __half22float2(((const __half2*)&g_h2s[(size_t)r0 * GNN_HID])[lane]);
        float2 v1 = __half22float2(((const __half2*)&g_h2s[(size_t)r1 * GNN_HID])[lane]);
        a0 += v0.x; a1 += v0.y;
        b0 += v1.x; b1 += v1.y;
        base += 2;
    }
    if (base < cnt) {
        int r0 = __ldg(&g_erow[start + base]);
        float2 v0 = __half22float2(((const __half2*)&g_h2s[(size_t)r0 * GNN_HID])[lane]);
        c0 += v0.x; c1 += v0.y;
    }

    float dv = g_dinv[node];
    int ch = lane * 2;
    float v0 = fmaxf(dv * ((a0 + b0) + (c0 + d0)) + __ldg(&b2[ch]), 0.0f);
    float v1 = fmaxf(dv * ((a1 + b1) + (c1 + d1)) + __ldg(&b2[ch + 1]), 0.0f);
    *(__half2*)&g_x2[(size_t)node * GNN_HID + ch] = __floats2half2_rn(v0, v1);
}

// Fused mean-pool + graph embedding -> fp16 cols [0,128)
__global__ __launch_bounds__(128) void k_poolgemb(const float* __restrict__ Wg,
                                                  const float* __restrict__ bg) {
    __shared__ float tmp[128];
    __shared__ float sp[GNN_HID];
    int b = blockIdx.x;
    int t = threadIdx.x;
    int s = g_gstart[b], e = g_gstart[b + 1];

    float acc = 0.0f;
    for (int i = s + (t >> 6); i < e; i += 2)
        acc += __half2float(g_x2[(size_t)i * GNN_HID + (t & 63)]);
    tmp[t] = acc;
    __syncthreads();
    if (t < GNN_HID) {
        float inv = 1.0f / fmaxf((float)(e - s), 1.0f);
        sp[t] = (tmp[t] + tmp[t + 64]) * inv;
    }
    __syncthreads();

    float g = bg[t];
#pragma unroll 8
    for (int j = 0; j < GNN_HID; j++) g += sp[j] * Wg[j * G_EMB + t];
    g_a16[(size_t)b * KP2 + t] = __float2half(g);
}

// Vectorized concat (proven form): 8 cols/thread, 2x LDG.128 + 1x STG.128.
__global__ __launch_bounds__(512) void k_concat(const float* __restrict__ comp,
                                                const float* __restrict__ prot) {
    int b = blockIdx.x;
    int t = threadIdx.x;
    if (t >= 496) return;                      // 496 * 8 = 3968 = KP2 - G_EMB
    int c0 = G_EMB + t * 8;
    float v[8];
#pragma unroll
    for (int j = 0; j < 8; j++) {
        int c = c0 + j;
        float x = 0.0f;
        if (c < G_EMB + COMP_DIM)      x = __ldg(&comp[(size_t)b * COMP_DIM + (c - G_EMB)]);
        else if (c < K_TOT)            x = __ldg(&prot[(size_t)b * PROT_DIM + (c - G_EMB - COMP_DIM)]);
        v[j] = x;
    }
    uint4 u;
    u.x = packh2(__float2half(v[0]), __float2half(v[1]));
    u.y = packh2(__float2half(v[2]), __float2half(v[3]));
    u.z = packh2(__float2half(v[4]), __float2half(v[5]));
    u.w = packh2(__float2half(v[6]), __float2half(v[7]));
    *(uint4*)&g_a16[(size_t)b * KP2 + c0] = u;
}

// Wf1 [4051,256] -> transposed padded fp16 [256][4096]
__global__ __launch_bounds__(1024) void k_padWt(const float* __restrict__ Wf1) {
    __shared__ float tile[32][33];
    int k0 = blockIdx.x * 32;
    int n0 = blockIdx.y * 32;
    int tx = threadIdx.x, ty = threadIdx.y;
    int k = k0 + ty, n = n0 + tx;
    tile[ty][tx] = (k < K_TOT) ? Wf1[(size_t)k * HID + n] : 0.0f;
    __syncthreads();
    float v = tile[tx][ty];
    size_t o = (size_t)(n0 + ty) * KP2 + (k0 + tx);
    g_w16[o] = __float2half(v);
}

// -------------------- fp16 1-pass mma GEMM (ldmatrix) + fused epilogue --------------------

__device__ __forceinline__ void stage_loads(uint32_t sbase, int m0, int kt, int tid) {
    size_t kof = (size_t)kt * BK;
    {
        int r = tid >> 2, seg = tid & 3;
        uint32_t d = sbase + r * (SKA * 2) + seg * 16;
        CP16(d + OFF_A, &g_a16[(size_t)(m0 + r) * KP2 + kof + seg * 8]);
    }
#pragma unroll
    for (int it = 0; it < 2; it++) {
        int idx = tid + it * THR;
        int r = idx >> 2, seg = idx & 3;
        uint32_t d = sbase + r * (SKA * 2) + seg * 16;
        CP16(d + OFF_B, &g_w16[(size_t)r * KP2 + kof + seg * 8]);
    }
}

__global__ void __launch_bounds__(THR, 1) k_gemm_mma(const float* __restrict__ bf1,
                                                     const float* __restrict__ Wf2,
                                                     const float* __restrict__ bf2,
                                                     float* __restrict__ out) {
    extern __shared__ char smem[];
    uint32_t sb = s2u(smem);
    int tid = threadIdx.x;
    int wid = tid >> 5, lane = tid & 31;
    int mw = wid >> 2, nw = wid & 3;
    int g = lane >> 2, tig = lane & 3;
    int m0 = blockIdx.x * BM;

    int a_lrow = (lane & 7) + ((lane >> 3) & 1) * 8;
    int a_lcol = ((lane >> 4) & 1) * 8;
    int b_lrow = (lane & 7) + ((lane >> 4) & 1) * 8;
    int b_lcol = ((lane >> 3) & 1) * 8;

    float* s_bf1 = (float*)(smem + OFF_BF1);
    float* s_wf2 = (float*)(smem + OFF_WF2);
    float* s_red = (float*)(smem + OFF_RED);
    if (tid < HID) { s_bf1[tid] = bf1[tid]; s_wf2[tid] = Wf2[tid]; }

    float acc[2][8][4];
#pragma unroll
    for (int mt = 0; mt < 2; mt++)
#pragma unroll
        for (int nt = 0; nt < 8; nt++)
#pragma unroll
            for (int e = 0; e < 4; e++) acc[mt][nt][e] = 0.0f;

    stage_loads(sb + 0 * STAGE_SZ, m0, 0, tid);
    asm volatile("cp.async.commit_group;" ::: "memory");
    stage_loads(sb + 1 * STAGE_SZ, m0, 1, tid);
    asm volatile("cp.async.commit_group;" ::: "memory");

    for (int i = 0; i < NCHUNK; i++) {
        int cur = i % NSTAGE;
        uint32_t stg = sb + cur * STAGE_SZ;
        if (i + 2 < NCHUNK) {
            stage_loads(sb + ((i + 2) % NSTAGE) * STAGE_SZ, m0, i + 2, tid);
            asm volatile("cp.async.commit_group;" ::: "memory");
            asm volatile("cp.async.wait_group 2;" ::: "memory");
        } else if (i + 1 < NCHUNK) {
            asm volatile("cp.async.wait_group 1;" ::: "memory");
        } else {
            asm volatile("cp.async.wait_group 0;" ::: "memory");
        }
        __syncthreads();

        uint32_t aA = stg + OFF_A;
        uint32_t aB = stg + OFF_B;
#pragma unroll
        for (int kk = 0; kk < 2; kk++) {
            int kc = kk * 16;
            uint32_t a[2][4], b[8][2];
#pragma unroll
            for (int mt = 0; mt < 2; mt++) {
                uint32_t addr = aA + (uint32_t)(mw * 32 + mt * 16 + a_lrow) * (SKA * 2)
                              + (uint32_t)(kc + a_lcol) * 2;
                ldsm4(a[mt][0], a[mt][1], a[mt][2], a[mt][3], addr);
            }
#pragma unroll
            for (int np = 0; np < 4; np++) {
                int nt = np * 2;
                uint32_t addr = aB + (uint32_t)(nw * 64 + nt * 8 + b_lrow) * (SKA * 2)
                              + (uint32_t)(kc + b_lcol) * 2;
                ldsm4(b[nt][0], b[nt][1], b[nt + 1][0], b[nt + 1][1], addr);
            }
#pragma unroll
            for (int mt = 0; mt < 2; mt++)
#pragma unroll
                for (int nt = 0; nt < 8; nt++)
                    mma16816h(acc[mt][nt], a[mt], b[nt]);
        }
        __syncthreads();
    }

#pragma unroll
    for (int mt = 0; mt < 2; mt++) {
#pragma unroll
        for (int half = 0; half < 2; half++) {
            int rowl = mw * 32 + mt * 16 + half * 8 + g;
            float p = 0.0f;
#pragma unroll
            for (int nt = 0; nt < 8; nt++) {
                int col = nw * 64 + nt * 8 + tig * 2;
                float v0 = fmaxf(acc[mt][nt][half * 2 + 0] + s_bf1[col], 0.0f);
                float v1 = fmaxf(acc[mt][nt][half * 2 + 1] + s_bf1[col + 1], 0.0f);
                p = fmaf(v0, s_wf2[col], p);
                p = fmaf(v1, s_wf2[col + 1], p);
            }
            p += __shfl_xor_sync(0xFFFFFFFFu, p, 1);
            p += __shfl_xor_sync(0xFFFFFFFFu, p, 2);
            if (tig == 0) s_red[rowl * 4 + nw] = p;
        }
    }
    __syncthreads();
    if (tid < BM) {
        float z = s_red[tid * 4] + s_red[tid * 4 + 1] + s_red[tid * 4 + 2] +
                  s_red[tid * 4 + 3] + bf2[0];
        out[m0 + tid] = 1.0f / (1.0f + expf(-z));
    }
}

// -------------------- launch --------------------
extern "C" void kernel_launch(void* const* d_in, const int* in_sizes, int n_in,
                              void* d_out, int out_size) {
    const float* node_x = (const float*)d_in[0];
    const float* comp   = (const float*)d_in[1];
    const float* prot   = (const float*)d_in[2];
    const int*   ei     = (const int*)d_in[3];
    const int*   batch  = (const int*)d_in[4];
    const float* W1     = (const float*)d_in[5];
    const float* b1     = (const float*)d_in[6];
    const float* W2     = (const float*)d_in[7];
    const float* b2     = (const float*)d_in[8];
    const float* Wg     = (const float*)d_in[9];
    const float* bg     = (const float*)d_in[10];
    const float* Wf1    = (const float*)d_in[11];
    const float* bf1    = (const float*)d_in[12];
    const float* Wf2    = (const float*)d_in[13];
    const float* bf2    = (const float*)d_in[14];
    float* out = (float*)d_out;

    static cudaStream_t s1 = nullptr;
    static cudaEvent_t evF = nullptr, evJ = nullptr;
    static bool attrs_set = false;
    if (!s1) {
        cudaStreamCreateWithFlags(&s1, cudaStreamNonBlocking);
        cudaEventCreateWithFlags(&evF, cudaEventDisableTiming);
        cudaEventCreateWithFlags(&evJ, cudaEventDisableTiming);
    }
    if (!attrs_set) {
        cudaFuncSetAttribute(k_layer2t, cudaFuncAttributeMaxDynamicSharedMemorySize, L2_SMEM);
        cudaFuncSetAttribute(k_gemm_mma, cudaFuncAttributeMaxDynamicSharedMemorySize, SMEM_BYTES);
        attrs_set = true;
    }

    // fork: side stream runs input-only streaming kernels
    cudaEventRecord(evF, 0);
    cudaStreamWaitEvent(s1, evF, 0);
    k_concat<<<N_GRAPHS, 512, 0, s1>>>(comp, prot);
    {
        dim3 grid(KP2 / 32, HID / 32);
        dim3 blk(32, 32);
        k_padWt<<<grid, blk, 0, s1>>>(Wf1);
    }
    cudaEventRecord(evJ, s1);

    // main chain (graph pipeline) — k_init removed (bounds in scan1; ecnt reset in gather)
    k_hist<<<(N_EDGES + 255) / 256, 256>>>(ei);
    k_scan1<<<NSCAN_BLKS, SCAN_BLK>>>(node_x, batch);
    k_scan2<<<1, NSCAN_BLKS>>>();
    k_scan3<<<NSCAN_BLKS, SCAN_BLK>>>();
    k_bucket_scat<<<(N_EDGES + 255) / 256, 256>>>(ei);
    k_layer2t<<<N_NODES / 128, 256, L2_SMEM>>>(W1, b1, W2);
    k_gather<<<(N_NODES * 32) / 256, 256>>>(b2);
    k_poolgemb<<<N_GRAPHS, 128>>>(Wg, bg);

    // join: GEMM needs concat+padWt (s1) and poolgemb (main)
    cudaStreamWaitEvent(0, evJ, 0);
    k_gemm_mma<<<N_GRAPHS / BM, THR, SMEM_BYTES>>>(bf1, Wf2, bf2, out);
}

// round 17
// speedup vs baseline: 1.7107x; 1.7107x over previous
#include <cuda_runtime.h>
#include <cuda_fp16.h>
#include <cuda_bf16.h>
#include <math.h>
#include <stdint.h>

#define N_NODES  524288
#define N_EDGES  2097152
#define N_GRAPHS 16384
#define COMP_DIM 3539
#define PROT_DIM 384
#define GNN_HID  64
#define G_EMB    128
#define HID      256
#define K_TOT    (G_EMB + COMP_DIM + PROT_DIM)   /* 4051 */
#define KP2      4096

#define SCAN_BLK   1024
#define NSCAN_BLKS (N_NODES / SCAN_BLK)   /* 512 */

// -------------------- scratch (static device memory; no allocs) --------------------
__device__ float g_dinv[N_NODES];
__device__ float g_s[N_NODES];
__device__ float g_acc1[N_NODES];
__device__ __half g_h2s[N_NODES * GNN_HID];
__device__ __half g_x2[N_NODES * GNN_HID];
__device__ int g_gstart[N_GRAPHS + 1];
__device__ int g_ecnt[N_NODES];
__device__ int g_eoff[N_NODES];
__device__ int g_cur[N_NODES];
__device__ int g_bsum[NSCAN_BLKS];
__device__ int g_erow[N_EDGES];
__device__ __half g_a16[(size_t)N_GRAPHS * KP2];
__device__ __half g_w16[(size_t)HID * KP2];

// -------------------- helpers --------------------
__device__ __forceinline__ void split2b(float v, __nv_bfloat16& h, __nv_bfloat16& l) {
    h = __float2bfloat16(v);
    l = __float2bfloat16(v - __bfloat162float(h));
}

__device__ __forceinline__ uint32_t packh2(__half a, __half b) {
    return ((uint32_t)__half_as_ushort(b) << 16) | (uint32_t)__half_as_ushort(a);
}

__device__ __forceinline__ uint32_t s2u(const void* p) {
    uint32_t a;
    asm("{ .reg .u64 t; cvta.to.shared.u64 t, %1; cvt.u32.u64 %0, t; }" : "=r"(a) : "l"(p));
    return a;
}

#define CP16(dst, src) \
    asm volatile("cp.async.cg.shared.global [%0], [%1], 16;" :: "r"(dst), "l"(src) : "memory")

__device__ __forceinline__ void ldsm4(uint32_t& r0, uint32_t& r1, uint32_t& r2, uint32_t& r3,
                                      uint32_t addr) {
    asm volatile("ldmatrix.sync.aligned.m8n8.x4.shared.b16 {%0,%1,%2,%3}, [%4];"
                 : "=r"(r0), "=r"(r1), "=r"(r2), "=r"(r3) : "r"(addr));
}

__device__ __forceinline__ void mma16816h(float* c, const uint32_t* a, const uint32_t* b) {
    asm volatile(
        "mma.sync.aligned.m16n8k16.row.col.f32.f16.f16.f32 "
        "{%0,%1,%2,%3}, {%4,%5,%6,%7}, {%8,%9}, {%0,%1,%2,%3};"
        : "+f"(c[0]), "+f"(c[1]), "+f"(c[2]), "+f"(c[3])
        : "r"(a[0]), "r"(a[1]), "r"(a[2]), "r"(a[3]), "r"(b[0]), "r"(b[1]));
}

__device__ __forceinline__ void mma16816b(float* c, const uint32_t* a, const uint32_t* b) {
    asm volatile(
        "mma.sync.aligned.m16n8k16.row.col.f32.bf16.bf16.f32 "
        "{%0,%1,%2,%3}, {%4,%5,%6,%7}, {%8,%9}, {%0,%1,%2,%3};"
        : "+f"(c[0]), "+f"(c[1]), "+f"(c[2]), "+f"(c[3])
        : "r"(a[0]), "r"(a[1]), "r"(a[2]), "r"(a[3]), "r"(b[0]), "r"(b[1]));
}

// -------------------- GEMM geometry --------------------
#define BM 128
#define BN 256
#define BK 32
#define NCHUNK (KP2 / BK)     /* 128 */
#define NSTAGE 3
#define SKA 40
#define THR 512

#define SZ_A   (128 * SKA * 2)
#define SZ_B   (256 * SKA * 2)
#define OFF_A  0
#define OFF_B  (SZ_A)
#define STAGE_SZ (SZ_A + SZ_B)
#define OFF_BF1 (NSTAGE * STAGE_SZ)
#define OFF_WF2 (OFF_BF1 + 1024)
#define OFF_RED (OFF_WF2 + 1024)
#define SMEM_BYTES (OFF_RED + 2048)

// layer2t smem layout
#define L2_SU   0
#define L2_SDV  512
#define L2_SW1  1024
#define L2_SB1  1280
#define L2_XH   1536
#define L2_XL   (L2_XH + 20480)
#define L2_WH   (L2_XL + 20480)
#define L2_WL   (L2_WH + 10240)
#define L2_SMEM (L2_WL + 10240)

// -------------------- setup / bucketing kernels --------------------

__global__ void k_init(const int* __restrict__ batch) {
    int i = blockIdx.x * blockDim.x + threadIdx.x;
    if (i >= N_NODES) return;
    g_ecnt[i] = 0;
    int b = batch[i];
    if (i == 0) {
        for (int g = 0; g <= b; g++) g_gstart[g] = 0;
    } else {
        int bp = batch[i - 1];
        for (int g = bp + 1; g <= b; g++) g_gstart[g] = i;
    }
    if (i == N_NODES - 1) {
        for (int g = b + 1; g <= N_GRAPHS; g++) g_gstart[g] = N_NODES;
    }
}

__global__ void k_hist(const int* __restrict__ ei) {
    int e = blockIdx.x * blockDim.x + threadIdx.x;
    if (e < N_EDGES) atomicAdd(&g_ecnt[ei[N_EDGES + e]], 1);
}

// block scan + fused dinv/s/acc1
__global__ __launch_bounds__(SCAN_BLK) void k_scan1(const float* __restrict__ node_x) {
    __shared__ int sh[SCAN_BLK];
    int t = threadIdx.x;
    int base = blockIdx.x * SCAN_BLK;
    int i = base + t;
    int v = g_ecnt[i];
    sh[t] = v;
    __syncthreads();
#pragma unroll
    for (int off = 1; off < SCAN_BLK; off <<= 1) {
        int x = (t >= off) ? sh[t - off] : 0;
        __syncthreads();
        sh[t] += x;
        __syncthreads();
    }
    g_eoff[i] = sh[t] - v;
    if (t == SCAN_BLK - 1) g_bsum[blockIdx.x] = sh[t];
    float d = rsqrtf(1.0f + (float)v);
    g_dinv[i] = d;
    float s = d * node_x[i];
    g_s[i] = s;
    g_acc1[i] = s;
}

__global__ __launch_bounds__(NSCAN_BLKS) void k_scan2() {
    __shared__ int sh[NSCAN_BLKS];
    int t = threadIdx.x;
    int v = g_bsum[t];
    sh[t] = v;
    __syncthreads();
#pragma unroll
    for (int off = 1; off < NSCAN_BLKS; off <<= 1) {
        int x = (t >= off) ? sh[t - off] : 0;
        __syncthreads();
        sh[t] += x;
        __syncthreads();
    }
    g_bsum[t] = sh[t] - v;
}

__global__ __launch_bounds__(SCAN_BLK) void k_scan3() {
    int i = blockIdx.x * SCAN_BLK + threadIdx.x;
    int o = g_eoff[i] + g_bsum[blockIdx.x];
    g_eoff[i] = o;
    g_cur[i] = o;
}

// Fused: bucket fill + layer-1 scalar scatter (single pass over edges)
__global__ void k_bucket_scat(const int* __restrict__ ei) {
    int e = blockIdx.x * blockDim.x + threadIdx.x;
    if (e < N_EDGES) {
        int r = ei[e];
        int c = ei[N_EDGES + e];
        int pos = atomicAdd(&g_cur[c], 1);
        g_erow[pos] = r;
        atomicAdd(&g_acc1[c], g_s[r]);
    }
}

// Tensor-core layer2 (bf16 3-pass, proven): h2s = dinv*(x1@W2) -> fp16
__global__ void __launch_bounds__(256) k_layer2t(const float* __restrict__ W1,
                                                 const float* __restrict__ b1,
                                                 const float* __restrict__ W2) {
    extern __shared__ char sm[];
    float* su  = (float*)(sm + L2_SU);
    float* sdv = (float*)(sm + L2_SDV);
    float* sW1 = (float*)(sm + L2_SW1);
    float* sb1 = (float*)(sm + L2_SB1);
    __nv_bfloat16* sXh = (__nv_bfloat16*)(sm + L2_XH);
    __nv_bfloat16* sXl = (__nv_bfloat16*)(sm + L2_XL);
    __nv_bfloat16* sWh = (__nv_bfloat16*)(sm + L2_WH);
    __nv_bfloat16* sWl = (__nv_bfloat16*)(sm + L2_WL);

    int tid = threadIdx.x;
    int node0 = blockIdx.x * 128;

    if (tid < 64) { sW1[tid] = W1[tid]; sb1[tid] = b1[tid]; }
    if (tid < 128) {
        int n = node0 + tid;
        float dv = g_dinv[n];
        sdv[tid] = dv;
        su[tid] = dv * g_acc1[n];
    }
    for (int idx = tid; idx < 64 * 64; idx += 256) {
        int k = idx >> 6, n = idx & 63;
        __nv_bfloat16 h, l;
        split2b(W2[idx], h, l);
        int off = (k >> 5) * (64 * SKA) + n * SKA + (k & 31);
        sWh[off] = h; sWl[off] = l;
    }
    __syncthreads();

    for (int idx = tid; idx < 128 * 64; idx += 256) {
        int m = idx >> 6, k = idx & 63;
        float x = fmaxf(su[m] * sW1[k] + sb1[k], 0.0f);
        __nv_bfloat16 h, l;
        split2b(x, h, l);
        int off = (k >> 5) * (128 * SKA) + m * SKA + (k & 31);
        sXh[off] = h; sXl[off] = l;
    }
    __syncthreads();

    int wid = tid >> 5, lane = tid & 31;
    int mw = wid >> 1, nw = wid & 1;
    int g = lane >> 2, tig = lane & 3;

    float acc[2][4][4];
#pragma unroll
    for (int mt = 0; mt < 2; mt++)
#pragma unroll
        for (int nt = 0; nt < 4; nt++)
#pragma unroll
            for (int e = 0; e < 4; e++) acc[mt][nt][e] = 0.0f;

#pragma unroll
    for (int ks = 0; ks < 4; ks++) {
        int ch = ks >> 1, kc = (ks & 1) * 16;
        const __nv_bfloat16* Ah = sXh + ch * (128 * SKA);
        const __nv_bfloat16* Al = sXl + ch * (128 * SKA);
        const __nv_bfloat16* Bh = sWh + ch * (64 * SKA);
        const __nv_bfloat16* Bl = sWl + ch * (64 * SKA);
        uint32_t a[2][4], b[4][2];
#pragma unroll
        for (int mt = 0; mt < 2; mt++) {
            const __nv_bfloat16* p = Al + (mw * 32 + mt * 16 + g) * SKA + kc + tig * 2;
            a[mt][0] = *(const uint32_t*)p;
            a[mt][1] = *(const uint32_t*)(p + 8 * SKA);
            a[mt][2] = *(const uint32_t*)(p + 8);
            a[mt][3] = *(const uint32_t*)(p + 8 * SKA + 8);
        }
#pragma unroll
        for (int nt = 0; nt < 4; nt++) {
            const __nv_bfloat16* p = Bh + (nw * 32 + nt * 8 + g) * SKA + kc + tig * 2;
            b[nt][0] = *(const uint32_t*)p;
            b[nt][1] = *(const uint32_t*)(p + 8);
        }
#pragma unroll
        for (int mt = 0; mt < 2; mt++)
#pragma unroll
            for (int nt = 0; nt < 4; nt++) mma16816b(acc[mt][nt], a[mt], b[nt]);
#pragma unroll
        for (int mt = 0; mt < 2; mt++) {
            const __nv_bfloat16* p = Ah + (mw * 32 + mt * 16 + g) * SKA + kc + tig * 2;
            a[mt][0] = *(const uint32_t*)p;
            a[mt][1] = *(const uint32_t*)(p + 8 * SKA);
            a[mt][2] = *(const uint32_t*)(p + 8);
            a[mt][3] = *(const uint32_t*)(p + 8 * SKA + 8);
        }
#pragma unroll
        for (int mt = 0; mt < 2; mt++)
#pragma unroll
            for (int nt = 0; nt < 4; nt++) mma16816b(acc[mt][nt], a[mt], b[nt]);
#pragma unroll
        for (int nt = 0; nt < 4; nt++) {
            const __nv_bfloat16* p = Bl + (nw * 32 + nt * 8 + g) * SKA + kc + tig * 2;
            b[nt][0] = *(const uint32_t*)p;
            b[nt][1] = *(const uint32_t*)(p + 8);
        }
#pragma unroll
        for (int mt = 0; mt < 2; mt++)
#pragma unroll
            for (int nt = 0; nt < 4; nt++) mma16816b(acc[mt][nt], a[mt], b[nt]);
    }

#pragma unroll
    for (int mt = 0; mt < 2; mt++) {
        int r0 = mw * 32 + mt * 16 + g;
        float dv0 = sdv[r0], dv1 = sdv[r0 + 8];
#pragma unroll
        for (int nt = 0; nt < 4; nt++) {
            int col = nw * 32 + nt * 8 + tig * 2;
            size_t o0 = (size_t)(node0 + r0) * GNN_HID + col;
            size_t o1 = (size_t)(node0 + r0 + 8) * GNN_HID + col;
            *(__half2*)&g_h2s[o0] =
                __floats2half2_rn(dv0 * acc[mt][nt][0], dv0 * acc[mt][nt][1]);
            *(__half2*)&g_h2s[o1] =
                __floats2half2_rn(dv1 * acc[mt][nt][2], dv1 * acc[mt][nt][3]);
        }
    }
}

// Gather + relu -> x2 (fp16). One warp per node; lane owns channels (2l, 2l+1).
__global__ void k_gather(const float* __restrict__ b2) {
    int gt = blockIdx.x * blockDim.x + threadIdx.x;
    int node = gt >> 5;
    int lane = gt & 31;
    if (node >= N_NODES) return;

    int start = g_eoff[node];
    int cnt = g_ecnt[node];
    const __half2* selfp = (const __half2*)&g_h2s[(size_t)node * GNN_HID];
    float2 sv = __half22float2(selfp[lane]);
    float a0 = sv.x, a1 = sv.y;
    float b0 = 0.f, b1 = 0.f, c0 = 0.f, c1 = 0.f, d0 = 0.f, d1 = 0.f;

    int base = 0;
    for (; base + 4 <= cnt; base += 4) {
        int r0 = __ldg(&g_erow[start + base + 0]);
        int r1 = __ldg(&g_erow[start + base + 1]);
        int r2 = __ldg(&g_erow[start + base + 2]);
        int r3 = __ldg(&g_erow[start + base + 3]);
        float2 v0 = __half22float2(((const __half2*)&g_h2s[(size_t)r0 * GNN_HID])[lane]);
        float2 v1 = __half22float2(((const __half2*)&g_h2s[(size_t)r1 * GNN_HID])[lane]);
        float2 v2 = __half22float2(((const __half2*)&g_h2s[(size_t)r2 * GNN_HID])[lane]);
        float2 v3 = __half22float2(((const __half2*)&g_h2s[(size_t)r3 * GNN_HID])[lane]);
        a0 += v0.x; a1 += v0.y;
        b0 += v1.x; b1 += v1.y;
        c0 += v2.x; c1 += v2.y;
        d0 += v3.x; d1 += v3.y;
    }
    if (base + 2 <= cnt) {
        int r0 = __ldg(&g_erow[start + base + 0]);
        int r1 = __ldg(&g_erow[start + base + 1]);
        float2 v0 = __half22float2(((const __half2*)&g_h2s[(size_t)r0 * GNN_HID])[lane]);
        float2 v1 = __half22float2(((const __half2*)&g_h2s[(size_t)r1 * GNN_HID])[lane]);
        a0 += v0.x; a1 += v0.y;
        b0 += v1.x; b1 += v1.y;
        base += 2;
    }
    if (base < cnt) {
        int r0 = __ldg(&g_erow[start + base]);
        float2 v0 = __half22float2(((const __half2*)&g_h2s[(size_t)r0 * GNN_HID])[lane]);
        c0 += v0.x; c1 += v0.y;
    }

    float dv = g_dinv[node];
    int ch = lane * 2;
    float v0 = fmaxf(dv * ((a0 + b0) + (c0 + d0)) + __ldg(&b2[ch]), 0.0f);
    float v1 = fmaxf(dv * ((a1 + b1) + (c1 + d1)) + __ldg(&b2[ch + 1]), 0.0f);
    *(__half2*)&g_x2[(size_t)node * GNN_HID + ch] = __floats2half2_rn(v0, v1);
}

// Fused mean-pool + graph embedding -> fp16 cols [0,128)
__global__ __launch_bounds__(128) void k_poolgemb(const float* __restrict__ Wg,
                                                  const float* __restrict__ bg) {
    __shared__ float tmp[128];
    __shared__ float sp[GNN_HID];
    int b = blockIdx.x;
    int t = threadIdx.x;
    int s = g_gstart[b], e = g_gstart[b + 1];

    float acc = 0.0f;
    for (int i = s + (t >> 6); i < e; i += 2)
        acc += __half2float(g_x2[(size_t)i * GNN_HID + (t & 63)]);
    tmp[t] = acc;
    __syncthreads();
    if (t < GNN_HID) {
        float inv = 1.0f / fmaxf((float)(e - s), 1.0f);
        sp[t] = (tmp[t] + tmp[t + 64]) * inv;
    }
    __syncthreads();

    float g = bg[t];
#pragma unroll 8
    for (int j = 0; j < GNN_HID; j++) g += sp[j] * Wg[j * G_EMB + t];
    g_a16[(size_t)b * KP2 + t] = __float2half(g);
}

// Vectorized concat (proven form): 8 cols/thread, 2x LDG.128 + 1x STG.128.
__global__ __launch_bounds__(512) void k_concat(const float* __restrict__ comp,
                                                const float* __restrict__ prot) {
    int b = blockIdx.x;
    int t = threadIdx.x;
    if (t >= 496) return;                      // 496 * 8 = 3968 = KP2 - G_EMB
    int c0 = G_EMB + t * 8;
    float v[8];
#pragma unroll
    for (int j = 0; j < 8; j++) {
        int c = c0 + j;
        float x = 0.0f;
        if (c < G_EMB + COMP_DIM)      x = __ldg(&comp[(size_t)b * COMP_DIM + (c - G_EMB)]);
        else if (c < K_TOT)            x = __ldg(&prot[(size_t)b * PROT_DIM + (c - G_EMB - COMP_DIM)]);
        v[j] = x;
    }
    uint4 u;
    u.x = packh2(__float2half(v[0]), __float2half(v[1]));
    u.y = packh2(__float2half(v[2]), __float2half(v[3]));
    u.z = packh2(__float2half(v[4]), __float2half(v[5]));
    u.w = packh2(__float2half(v[6]), __float2half(v[7]));
    *(uint4*)&g_a16[(size_t)b * KP2 + c0] = u;
}

// Wf1 [4051,256] -> transposed padded fp16 [256][4096]
__global__ __launch_bounds__(1024) void k_padWt(const float* __restrict__ Wf1) {
    __shared__ float tile[32][33];
    int k0 = blockIdx.x * 32;
    int n0 = blockIdx.y * 32;
    int tx = threadIdx.x, ty = threadIdx.y;
    int k = k0 + ty, n = n0 + tx;
    tile[ty][tx] = (k < K_TOT) ? Wf1[(size_t)k * HID + n] : 0.0f;
    __syncthreads();
    float v = tile[tx][ty];
    size_t o = (size_t)(n0 + ty) * KP2 + (k0 + tx);
    g_w16[o] = __float2half(v);
}

// -------------------- fp16 1-pass mma GEMM (ldmatrix) + fused epilogue --------------------

__device__ __forceinline__ void stage_loads(uint32_t sbase, int m0, int kt, int tid) {
    size_t kof = (size_t)kt * BK;
    {
        int r = tid >> 2, seg = tid & 3;
        uint32_t d = sbase + r * (SKA * 2) + seg * 16;
        CP16(d + OFF_A, &g_a16[(size_t)(m0 + r) * KP2 + kof + seg * 8]);
    }
#pragma unroll
    for (int it = 0; it < 2; it++) {
        int idx = tid + it * THR;
        int r = idx >> 2, seg = idx & 3;
        uint32_t d = sbase + r * (SKA * 2) + seg * 16;
        CP16(d + OFF_B, &g_w16[(size_t)r * KP2 + kof + seg * 8]);
    }
}

__global__ void __launch_bounds__(THR, 1) k_gemm_mma(const float* __restrict__ bf1,
                                                     const float* __restrict__ Wf2,
                                                     const float* __restrict__ bf2,
                                                     float* __restrict__ out) {
    extern __shared__ char smem[];
    uint32_t sb = s2u(smem);
    int tid = threadIdx.x;
    int wid = tid >> 5, lane = tid & 31;
    int mw = wid >> 2, nw = wid & 3;
    int g = lane >> 2, tig = lane & 3;
    int m0 = blockIdx.x * BM;

    int a_lrow = (lane & 7) + ((lane >> 3) & 1) * 8;
    int a_lcol = ((lane >> 4) & 1) * 8;
    int b_lrow = (lane & 7) + ((lane >> 4) & 1) * 8;
    int b_lcol = ((lane >> 3) & 1) * 8;

    float* s_bf1 = (float*)(smem + OFF_BF1);
    float* s_wf2 = (float*)(smem + OFF_WF2);
    float* s_red = (float*)(smem + OFF_RED);
    if (tid < HID) { s_bf1[tid] = bf1[tid]; s_wf2[tid] = Wf2[tid]; }

    float acc[2][8][4];
#pragma unroll
    for (int mt = 0; mt < 2; mt++)
#pragma unroll
        for (int nt = 0; nt < 8; nt++)
#pragma unroll
            for (int e = 0; e < 4; e++) acc[mt][nt][e] = 0.0f;

    stage_loads(sb + 0 * STAGE_SZ, m0, 0, tid);
    asm volatile("cp.async.commit_group;" ::: "memory");
    stage_loads(sb + 1 * STAGE_SZ, m0, 1, tid);
    asm volatile("cp.async.commit_group;" ::: "memory");

    for (int i = 0; i < NCHUNK; i++) {
        int cur = i % NSTAGE;
        uint32_t stg = sb + cur * STAGE_SZ;
        if (i + 2 < NCHUNK) {
            stage_loads(sb + ((i + 2) % NSTAGE) * STAGE_SZ, m0, i + 2, tid);
            asm volatile("cp.async.commit_group;" ::: "memory");
            asm volatile("cp.async.wait_group 2;" ::: "memory");
        } else if (i + 1 < NCHUNK) {
            asm volatile("cp.async.wait_group 1;" ::: "memory");
        } else {
            asm volatile("cp.async.wait_group 0;" ::: "memory");
        }
        __syncthreads();

        uint32_t aA = stg + OFF_A;
        uint32_t aB = stg + OFF_B;
#pragma unroll
        for (int kk = 0; kk < 2; kk++) {
            int kc = kk * 16;
            uint32_t a[2][4], b[8][2];
#pragma unroll
            for (int mt = 0; mt < 2; mt++) {
                uint32_t addr = aA + (uint32_t)(mw * 32 + mt * 16 + a_lrow) * (SKA * 2)
                              + (uint32_t)(kc + a_lcol) * 2;
                ldsm4(a[mt][0], a[mt][1], a[mt][2], a[mt][3], addr);
            }
#pragma unroll
            for (int np = 0; np < 4; np++) {
                int nt = np * 2;
                uint32_t addr = aB + (uint32_t)(nw * 64 + nt * 8 + b_lrow) * (SKA * 2)
                              + (uint32_t)(kc + b_lcol) * 2;
                ldsm4(b[nt][0], b[nt][1], b[nt + 1][0], b[nt + 1][1], addr);
            }
#pragma unroll
            for (int mt = 0; mt < 2; mt++)
#pragma unroll
                for (int nt = 0; nt < 8; nt++)
                    mma16816h(acc[mt][nt], a[mt], b[nt]);
        }
        __syncthreads();
    }

#pragma unroll
    for (int mt = 0; mt < 2; mt++) {
#pragma unroll
        for (int half = 0; half < 2; half++) {
            int rowl = mw * 32 + mt * 16 + half * 8 + g;
            float p = 0.0f;
#pragma unroll
            for (int nt = 0; nt < 8; nt++) {
                int col = nw * 64 + nt * 8 + tig * 2;
                float v0 = fmaxf(acc[mt][nt][half * 2 + 0] + s_bf1[col], 0.0f);
                float v1 = fmaxf(acc[mt][nt][half * 2 + 1] + s_bf1[col + 1], 0.0f);
                p = fmaf(v0, s_wf2[col], p);
                p = fmaf(v1, s_wf2[col + 1], p);
            }
            p += __shfl_xor_sync(0xFFFFFFFFu, p, 1);
            p += __shfl_xor_sync(0xFFFFFFFFu, p, 2);
            if (tig == 0) s_red[rowl * 4 + nw] = p;
        }
    }
    __syncthreads();
    if (tid < BM) {
        float z = s_red[tid * 4] + s_red[tid * 4 + 1] + s_red[tid * 4 + 2] +
                  s_red[tid * 4 + 3] + bf2[0];
        out[m0 + tid] = 1.0f / (1.0f + expf(-z));
    }
}

// -------------------- launch --------------------
extern "C" void kernel_launch(void* const* d_in, const int* in_sizes, int n_in,
                              void* d_out, int out_size) {
    const float* node_x = (const float*)d_in[0];
    const float* comp   = (const float*)d_in[1];
    const float* prot   = (const float*)d_in[2];
    const int*   ei     = (const int*)d_in[3];
    const int*   batch  = (const int*)d_in[4];
    const float* W1     = (const float*)d_in[5];
    const float* b1     = (const float*)d_in[6];
    const float* W2     = (const float*)d_in[7];
    const float* b2     = (const float*)d_in[8];
    const float* Wg     = (const float*)d_in[9];
    const float* bg     = (const float*)d_in[10];
    const float* Wf1    = (const float*)d_in[11];
    const float* bf1    = (const float*)d_in[12];
    const float* Wf2    = (const float*)d_in[13];
    const float* bf2    = (const float*)d_in[14];
    float* out = (float*)d_out;

    static cudaStream_t s1 = nullptr;
    static cudaEvent_t evF = nullptr, evJ = nullptr;
    static bool attrs_set = false;
    if (!s1) {
        cudaStreamCreateWithFlags(&s1, cudaStreamNonBlocking);
        cudaEventCreateWithFlags(&evF, cudaEventDisableTiming);
        cudaEventCreateWithFlags(&evJ, cudaEventDisableTiming);
    }
    if (!attrs_set) {
        cudaFuncSetAttribute(k_layer2t, cudaFuncAttributeMaxDynamicSharedMemorySize, L2_SMEM);
        cudaFuncSetAttribute(k_gemm_mma, cudaFuncAttributeMaxDynamicSharedMemorySize, SMEM_BYTES);
        attrs_set = true;
    }

    // fork: side stream runs input-only streaming kernels
    cudaEventRecord(evF, 0);
    cudaStreamWaitEvent(s1, evF, 0);
    k_concat<<<N_GRAPHS, 512, 0, s1>>>(comp, prot);
    {
        dim3 grid(KP2 / 32, HID / 32);
        dim3 blk(32, 32);
        k_padWt<<<grid, blk, 0, s1>>>(Wf1);
    }
    cudaEventRecord(evJ, s1);

    // main chain (graph pipeline)
    k_init<<<(N_NODES + 255) / 256, 256>>>(batch);
    k_hist<<<(N_EDGES + 255) / 256, 256>>>(ei);
    k_scan1<<<NSCAN_BLKS, SCAN_BLK>>>(node_x);
    k_scan2<<<1, NSCAN_BLKS>>>();
    k_scan3<<<NSCAN_BLKS, SCAN_BLK>>>();
    k_bucket_scat<<<(N_EDGES + 255) / 256, 256>>>(ei);
    k_layer2t<<<N_NODES / 128, 256, L2_SMEM>>>(W1, b1, W2);
    k_gather<<<(N_NODES * 32) / 256, 256>>>(b2);
    k_poolgemb<<<N_GRAPHS, 128>>>(Wg, bg);

    // join: GEMM needs concat+padWt (s1) and poolgemb (main)
    cudaStreamWaitEvent(0, evJ, 0);
    k_gemm_mma<<<N_GRAPHS / BM, THR, SMEM_BYTES>>>(bf1, Wf2, bf2, out);
}